// round 16
// baseline (speedup 1.0000x reference)
#include <cuda_runtime.h>
#include <cuda_fp16.h>
#include <cstdint>
#include <math.h>

#define BB 128
#define TT 512
#define II 256
#define HH 1024
#define GG 4096
#define CC 1000
#define KTOT 1280
#define NCTA 128
#define NTHR 512           // xg_gemm
#define NTHR_P 256         // persistent recurrence
#define NCHUNK_H 8         // h-part K=1024 in 8 chunks of 128

// Persistent kernel SMEM: Whh slice 32x1024 fp16 only (A goes direct-LDG now)
#define W_HI 0u
#define SMEM_DYN (65536 + 256)

// Precompute kernel SMEM: B 64K | A_hi 64K | A_lo 64K
#define PRE_B  0u
#define PRE_AH 65536u
#define PRE_AL 131072u
#define SMEM_PRE (196608 + 256)

// ---------------- device globals (no dynamic alloc) ---------------------------
__device__ __align__(16) __half g_Wh[GG * KTOT];            // weights fp16, permuted rows
__device__ __align__(16) __half g_xh[TT * BB * II];         // x hi, [t][m][k]
__device__ __align__(16) __half g_xl[TT * BB * II];         // x lo
__device__ __align__(16) __half g_hh[2][BB * HH];           // h ping-pong, sigma-permuted cols
__device__ float g_bs[GG];
__device__ float g_xg[268435456];                           // [t][nb][m][32] = 1 GB
__device__ unsigned g_gc[8 * 32];                           // counters, 128B apart

// ---------------- helpers ------------------------------------------------------
__device__ __forceinline__ uint32_t smem_u32(const void* p) {
    uint32_t a;
    asm("{ .reg .u64 t; cvta.to.shared.u64 t, %1; cvt.u32.u64 %0, t; }" : "=r"(a) : "l"(p));
    return a;
}
__device__ __forceinline__ void cp16(uint32_t saddr, const void* gaddr) {
    asm volatile("cp.async.cg.shared.global [%0], [%1], 16;" :: "r"(saddr), "l"(gaddr) : "memory");
}
__device__ __forceinline__ void ldsm4(uint32_t addr, uint32_t& r0, uint32_t& r1,
                                      uint32_t& r2, uint32_t& r3) {
    asm volatile("ldmatrix.sync.aligned.m8n8.x4.shared.b16 {%0,%1,%2,%3}, [%4];"
                 : "=r"(r0), "=r"(r1), "=r"(r2), "=r"(r3) : "r"(addr));
}
__device__ __forceinline__ void mma16816(float* c, const uint32_t* a, uint32_t b0, uint32_t b1) {
    asm volatile(
        "mma.sync.aligned.m16n8k16.row.col.f32.f16.f16.f32 "
        "{%0,%1,%2,%3}, {%4,%5,%6,%7}, {%8,%9}, {%0,%1,%2,%3};"
        : "+f"(c[0]), "+f"(c[1]), "+f"(c[2]), "+f"(c[3])
        : "r"(a[0]), "r"(a[1]), "r"(a[2]), "r"(a[3]), "r"(b0), "r"(b1));
}

// ---------------- prep kernels -------------------------------------------------
// Stored row r = nb*32 + hc*4 + q  <->  original row q*H + nb*8 + hc. (unchanged)
__global__ void prep_w(const float* __restrict__ Wih, const float* __restrict__ Whh) {
    int idx = blockIdx.x * blockDim.x + threadIdx.x;
    if (idx >= GG * KTOT) return;
    int r = idx / KTOT, k = idx - r * KTOT;
    int nb = r >> 5, j = r & 31, hc = j >> 2, q = j & 3;
    int orig = q * HH + nb * 8 + hc;
    float v = (k < II) ? Wih[(size_t)orig * II + k] : Whh[(size_t)orig * HH + (k - II)];
    g_Wh[idx] = __float2half_rn(v);
}

__global__ void prep_x(const float* __restrict__ x) {
    int idx = blockIdx.x * blockDim.x + threadIdx.x;
    if (idx >= TT * BB * II) return;
    int t = idx / (BB * II);
    int rem = idx - t * (BB * II);
    int m = rem / II, k = rem - m * II;
    float v = x[((size_t)m * TT + t) * II + k];
    __half hi = __float2half_rn(v);
    g_xh[idx] = hi;
    g_xl[idx] = __float2half_rn(v - __half2float(hi));
}

__global__ void prep_misc(const float* __restrict__ bih, const float* __restrict__ bhh) {
    int i = blockIdx.x * blockDim.x + threadIdx.x;
    if (i < BB * HH) g_hh[0][i] = __float2half_rn(0.f);
    if (i < GG) g_bs[i] = bih[i] + bhh[i];
    if (i < 8 * 32) g_gc[i] = 0u;
}

// ---------------- xg precompute: xg[t] = (xhi+xlo) @ Wih_perm^T (unchanged) -----
__global__ __launch_bounds__(NTHR, 1) void xg_gemm() {
    extern __shared__ __align__(16) char dsm_raw[];
    const uint32_t dbase = (smem_u32(dsm_raw) + 127) & ~127u;

    const int tid = threadIdx.x;
    const int wid = tid >> 5, lid = tid & 31;
    const int wm = wid >> 1, wn = wid & 1;
    const int nt = blockIdx.x;
    const int t  = blockIdx.y;
    const int mi = lid >> 3, lr = lid & 7;

    const __half* __restrict__ xsh = g_xh + (size_t)t * (BB * II);
    const __half* __restrict__ xsl = g_xl + (size_t)t * (BB * II);

#pragma unroll
    for (int s = 0; s < 8; s++) {
        int idx = tid + NTHR * s;
        int row = idx >> 5, seg = idx & 31;
        uint32_t so = (uint32_t)(seg >> 3) * 16384u + (uint32_t)row * 128u
                    + (uint32_t)(((seg & 7) ^ (row & 7)) << 4);
        cp16(dbase + PRE_B + so, g_Wh + (size_t)(nt * 128 + row) * KTOT + seg * 8);
        cp16(dbase + PRE_AH + so, xsh + (size_t)row * II + seg * 8);
        cp16(dbase + PRE_AL + so, xsl + (size_t)row * II + seg * 8);
    }
    asm volatile("cp.async.commit_group;" ::: "memory");
    asm volatile("cp.async.wait_group 0;" ::: "memory");
    __syncthreads();

    float acc[8][4];
#pragma unroll
    for (int j = 0; j < 8; j++)
#pragma unroll
        for (int i = 0; i < 4; i++) acc[j][i] = 0.f;

    const int arow = wm * 16 + ((mi & 1) << 3) + lr;
    const int axor = arow & 7;

#pragma unroll
    for (int ks = 0; ks < 16; ks++) {
        uint32_t ah[4], al[4];
        {
            int ksega = (ks & 3) * 2 + (mi >> 1);
            uint32_t ad = dbase + PRE_AH + (uint32_t)(ks >> 2) * 16384u
                        + (uint32_t)arow * 128u + (uint32_t)((ksega ^ axor) << 4);
            ldsm4(ad, ah[0], ah[1], ah[2], ah[3]);
            ldsm4(ad + (PRE_AL - PRE_AH), al[0], al[1], al[2], al[3]);
        }
#pragma unroll
        for (int g = 0; g < 4; g++) {
            int brow = wn * 64 + g * 16 + ((mi >> 1) << 3) + lr;
            int ksegb = (ks & 3) * 2 + (mi & 1);
            uint32_t bd = dbase + PRE_B + (uint32_t)(ks >> 2) * 16384u
                        + (uint32_t)brow * 128u + (uint32_t)((ksegb ^ (brow & 7)) << 4);
            uint32_t bh[4];
            ldsm4(bd, bh[0], bh[1], bh[2], bh[3]);
            mma16816(acc[g * 2 + 0], ah, bh[0], bh[1]);
            mma16816(acc[g * 2 + 1], ah, bh[2], bh[3]);
            mma16816(acc[g * 2 + 0], al, bh[0], bh[1]);
            mma16816(acc[g * 2 + 1], al, bh[2], bh[3]);
        }
    }

    const int lq = lid & 3;
#pragma unroll
    for (int j = 0; j < 8; j++) {
        int c = wn * 64 + (j >> 1) * 16 + (j & 1) * 8 + lq * 2;
        int C = nt * 128 + c;
        int nbv = C >> 5, c31 = C & 31;
#pragma unroll
        for (int r = 0; r < 2; r++) {
            int m = wm * 16 + (lid >> 2) + r * 8;
            size_t idx = (((size_t)t * NCTA + nbv) * 128 + m) * 32 + c31;
            *reinterpret_cast<float2*>(g_xg + idx) =
                make_float2(acc[j][r * 2], acc[j][r * 2 + 1]);
        }
    }
}

// ---------------- persistent LSTM recurrence -----------------------------------
// 128 CTAs x 256 thr = 8 warps (8m x 1n, warp tile 16x32). A operand loaded
// DIRECTLY from gmem as mma fragments: h stored with sigma-permuted columns so
// lane q's four logical k-cols {2q,2q+1,2q+8,2q+9} are physical 4q..4q+3 = one
// 8B .cg load. No A smem, no cp.async pipe, no ldmatrix-A, zero CTA barriers in
// the time loop (per-warp red.release, need = 128*t). c-state in registers.
__global__ __launch_bounds__(NTHR_P, 1) void lstm_persist() {
    extern __shared__ __align__(16) char dsm_raw[];
    const uint32_t dbase = (smem_u32(dsm_raw) + 127) & ~127u;

    const int tid = threadIdx.x;
    const int wid = tid >> 5, lid = tid & 31;
    const int nb = blockIdx.x;
    const int grp = nb >> 4;                 // producer group 0..7
    const int mi = lid >> 3, lr = lid & 7;

    // ---- load Whh slice (32 rows x k 256..1280) into SMEM once ----
#pragma unroll
    for (int s = 0; s < 16; s++) {
        int idx = tid + NTHR_P * s;          // 0..4095
        int row = idx >> 7, kseg = idx & 127;
        size_t go = (size_t)(nb * 32 + row) * KTOT + II + kseg * 8;
        uint32_t so = (uint32_t)row * 2048u + (uint32_t)(kseg >> 3) * 128u
                    + (uint32_t)(((kseg & 7) ^ (row & 7)) << 4);
        cp16(dbase + W_HI + so, g_Wh + go);
    }
    asm volatile("cp.async.commit_group;" ::: "memory");
    asm volatile("cp.async.wait_group 0;" ::: "memory");
    __syncthreads();

    const int lq = lid & 3;
    const bool hasIF = (lq & 1) == 0;
    const int hcl = lq >> 1;

    const int rr = lid >> 2;                 // fragment row 0..7
    const int qq = lid & 3;                  // fragment k-quad
    const int wbase = wid * 16;              // this warp's 16 batch rows

    // B addressing (resident W), two n16 groups
    const int brow0 = ((mi >> 1) << 3) + lr;
    const int brow1 = 16 + brow0;
    const uint32_t bb0 = dbase + W_HI + (uint32_t)brow0 * 2048u;
    const uint32_t bb1 = dbase + W_HI + (uint32_t)brow1 * 2048u;
    const int bx0 = brow0 & 7, bx1 = brow1 & 7;

    float creg[4][2];
#pragma unroll
    for (int a = 0; a < 4; a++) { creg[a][0] = 0.f; creg[a][1] = 0.f; }

#pragma unroll 1
    for (int t = 0; t < TT; t++) {
        const __half* __restrict__ hsh = g_hh[t & 1];
        const unsigned need = 128u * (unsigned)t;

        // xg prefetch (independent; consumed at epilogue)
        float2 xgv[4][2];
        {
            const float* xb = g_xg + (((size_t)t * NCTA + nb) * 128) * 32;
            const int r0 = wbase + rr;
            const int c0 = lq * 2;
#pragma unroll
            for (int nf = 0; nf < 4; nf++)
#pragma unroll
                for (int r = 0; r < 2; r++)
                    xgv[nf][r] = *reinterpret_cast<const float2*>(
                        xb + (size_t)(r0 + r * 8) * 32 + c0 + nf * 8);
        }

        auto poll = [&](int i) {             // warp-converged acquire poll
            const int ck = (grp + i) & 7;
            unsigned v;
            asm volatile("ld.acquire.gpu.global.u32 %0, [%1];"
                         : "=r"(v) : "l"(&g_gc[ck << 5]) : "memory");
            while (v < need) {
                __nanosleep(32);
                asm volatile("ld.acquire.gpu.global.u32 %0, [%1];"
                             : "=r"(v) : "l"(&g_gc[ck << 5]) : "memory");
            }
        };
        // Direct fragment loads: per ks two 8B .cg loads -> (a0,a2),(a1,a3)
        auto ldA = [&](uint2 (&f)[8][2], int i) {
            const int ck = (grp + i) & 7;
            const __half* p0 = hsh + (size_t)(wbase + rr) * HH + ck * 128 + (qq << 2);
#pragma unroll
            for (int ks = 0; ks < 8; ks++) {
                f[ks][0] = __ldcg(reinterpret_cast<const uint2*>(p0 + ks * 16));
                f[ks][1] = __ldcg(reinterpret_cast<const uint2*>(p0 + 8 * HH + ks * 16));
            }
        };

        float acc[4][4];
#pragma unroll
        for (int a = 0; a < 4; a++)
#pragma unroll
            for (int i = 0; i < 4; i++) acc[a][i] = 0.f;

        auto doc = [&](uint2 (&f)[8][2], int i) {
            const int ck = (grp + i) & 7;
#pragma unroll
            for (int ks = 0; ks < 8; ks++) {
                uint32_t a[4] = { f[ks][0].x, f[ks][1].x, f[ks][0].y, f[ks][1].y };
                const int kseg = ck * 16 + ks * 2 + (mi & 1);
                const uint32_t ko = (uint32_t)(kseg >> 3) * 128u;
                uint32_t bh[4];
                ldsm4(bb0 + ko + (uint32_t)(((kseg & 7) ^ bx0) << 4),
                      bh[0], bh[1], bh[2], bh[3]);
                mma16816(acc[0], a, bh[0], bh[1]);
                mma16816(acc[1], a, bh[2], bh[3]);
                ldsm4(bb1 + ko + (uint32_t)(((kseg & 7) ^ bx1) << 4),
                      bh[0], bh[1], bh[2], bh[3]);
                mma16816(acc[2], a, bh[0], bh[1]);
                mma16816(acc[3], a, bh[2], bh[3]);
            }
        };

        uint2 fa[8][2], fb[8][2];
        poll(0); ldA(fa, 0);
        poll(1); ldA(fb, 1);

#pragma unroll 1
        for (int i = 0; i < NCHUNK_H; i += 2) {
            doc(fa, i);
            if (i + 2 < NCHUNK_H) { poll(i + 2); ldA(fa, i + 2); }
            doc(fb, i + 1);
            if (i + 3 < NCHUNK_H) { poll(i + 3); ldA(fb, i + 3); }
        }

        // ---- epilogue: xg + bias + LSTM update (c in regs), write h(t+1) ----
        // sigma: logical col nglob -> physical (nb>>1)*16 + nf*4 + (nb&1)*2 + hcl
        __half* __restrict__ hh_o = g_hh[(t + 1) & 1];
        const int rbase = wbase + rr;
        const int pcolbase = (nb >> 1) * 16 + (nb & 1) * 2 + hcl;
#pragma unroll
        for (int nf = 0; nf < 4; nf++) {
            const int nglob = nb * 8 + nf * 2 + hcl;
            const float bias0 = g_bs[(hasIF ? 0 : 2) * HH + nglob];
            const float bias1 = g_bs[(hasIF ? 1 : 3) * HH + nglob];
            float d0 = acc[nf][0] + xgv[nf][0].x + bias0;
            float d1 = acc[nf][1] + xgv[nf][0].y + bias1;
            float d2 = acc[nf][2] + xgv[nf][1].x + bias0;
            float d3 = acc[nf][3] + xgv[nf][1].y + bias1;
            float e0 = __shfl_xor_sync(0xFFFFFFFFu, d0, 1);
            float e1 = __shfl_xor_sync(0xFFFFFFFFu, d1, 1);
            float e2 = __shfl_xor_sync(0xFFFFFFFFu, d2, 1);
            float e3 = __shfl_xor_sync(0xFFFFFFFFu, d3, 1);
            if (hasIF) {
                const int pcol = pcolbase + nf * 4;
#pragma unroll
                for (int r = 0; r < 2; r++) {
                    float gi = r ? d2 : d0, gf = r ? d3 : d1;
                    float gg = r ? e2 : e0, go = r ? e3 : e1;
                    float iv = 1.f / (1.f + expf(-gi));
                    float fv = 1.f / (1.f + expf(-gf));
                    float gv = tanhf(gg);
                    float ov = 1.f / (1.f + expf(-go));
                    float cn = fv * creg[nf][r] + iv * gv;
                    creg[nf][r] = cn;
                    float hv = ov * tanhf(cn);
                    hh_o[(size_t)(rbase + r * 8) * HH + pcol] = __float2half_rn(hv);
                }
            }
        }
        __syncwarp();                        // order all lanes' stores
        if (lid == 0)
            asm volatile("red.release.gpu.global.add.u32 [%0], %1;"
                         :: "l"(&g_gc[grp << 5]), "r"(1u) : "memory");
    }
}

// ---------------- final FC (sigma-aware h reads) --------------------------------
__global__ __launch_bounds__(256) void fc_kernel(
    const float* __restrict__ fcW, const float* __restrict__ fcb, float* __restrict__ out) {
    int w = blockIdx.x * 8 + (threadIdx.x >> 5);
    int lane = threadIdx.x & 31;
    if (w >= BB * CC) return;
    int b = w / CC, c = w - b * CC;
    const __half* __restrict__ hh = g_hh[0] + (size_t)b * HH;   // TT even
    const float* __restrict__ wr = fcW + (size_t)c * HH;
    const int wl = lane & 15;   // constant within-16 logical offset per lane
    const int sig = (wl < 8) ? ((wl >> 1) * 4 + (wl & 1))
                             : (((wl - 8) >> 1) * 4 + 2 + (wl & 1));
    float s = 0.f;
#pragma unroll 4
    for (int k = lane; k < HH; k += 32)
        s += __half2float(hh[(k & ~15) + sig]) * wr[k];
#pragma unroll
    for (int o = 16; o; o >>= 1) s += __shfl_down_sync(0xFFFFFFFFu, s, o);
    if (lane == 0) out[b * CC + c] = s + fcb[c];
}

extern "C" void kernel_launch(void* const* d_in, const int* in_sizes, int n_in,
                              void* d_out, int out_size) {
    const float* x   = (const float*)d_in[0];
    const float* Wih = (const float*)d_in[1];
    const float* Whh = (const float*)d_in[2];
    const float* bih = (const float*)d_in[3];
    const float* bhh = (const float*)d_in[4];
    const float* fcW = (const float*)d_in[5];
    const float* fcb = (const float*)d_in[6];
    float* out = (float*)d_out;

    cudaFuncSetAttribute(xg_gemm, cudaFuncAttributeMaxDynamicSharedMemorySize, SMEM_PRE);
    cudaFuncSetAttribute(lstm_persist, cudaFuncAttributeMaxDynamicSharedMemorySize, SMEM_DYN);

    prep_w<<<(GG * KTOT + 255) / 256, 256>>>(Wih, Whh);
    prep_x<<<(TT * BB * II + 255) / 256, 256>>>(x);
    prep_misc<<<(BB * HH + 255) / 256, 256>>>(bih, bhh);
    xg_gemm<<<dim3(32, TT, 1), NTHR, SMEM_PRE>>>();
    lstm_persist<<<NCTA, NTHR_P, SMEM_DYN>>>();
    fc_kernel<<<(BB * CC + 7) / 8, 256>>>(fcW, fcb, out);
}